// round 14
// baseline (speedup 1.0000x reference)
#include <cuda_runtime.h>
#include <cstdint>

#define N_SEQ 512
#define N_RES 384
#define CM    256
#define CO    32
#define CZ    128
#define BC    12288          /* N_RES * CO */
#define LN_EPS 1e-5f
#define EPS    1e-3f

// ---------------- scratch (__device__ globals: alloc-free) ----------------
__device__ float g_L[(size_t)BC * N_SEQ];      // [bc][a]  K-major  (25 MB)
__device__ float g_R[(size_t)BC * N_SEQ];      // [de][a]  K-major  (25 MB)
__device__ float g_norm[N_RES * N_RES];        // [b][d]
__device__ float g_WtT[CZ * 1024];             // [f][k=c*32+e]  tf32-rounded

// ---------------- helpers ----------------
__device__ __forceinline__ float rna_tf32(float x) {
    float y;
    asm("cvt.rna.tf32.f32 %0, %1;" : "=f"(y) : "f"(x));
    return y;
}
__device__ __forceinline__ void mma8(float d[4], const uint32_t a[4], const uint32_t b[2]) {
    asm volatile(
        "mma.sync.aligned.m16n8k8.row.col.f32.tf32.tf32.f32 "
        "{%0,%1,%2,%3}, {%4,%5,%6,%7}, {%8,%9}, {%0,%1,%2,%3};\n"
        : "+f"(d[0]), "+f"(d[1]), "+f"(d[2]), "+f"(d[3])
        : "r"(a[0]), "r"(a[1]), "r"(a[2]), "r"(a[3]),
          "r"(b[0]), "r"(b[1]));
}
__device__ __forceinline__ void ldsm4(uint32_t r[4], uint32_t addr) {
    asm volatile("ldmatrix.sync.aligned.m8n8.x4.shared.b16 {%0,%1,%2,%3}, [%4];"
        : "=r"(r[0]), "=r"(r[1]), "=r"(r[2]), "=r"(r[3]) : "r"(addr));
}
__device__ __forceinline__ void cpa16(uint32_t dst, const void* src) {
    asm volatile("cp.async.cg.shared.global [%0], [%1], 16;" :: "r"(dst), "l"(src));
}
#define CP_COMMIT() asm volatile("cp.async.commit_group;" ::: "memory")
#define CP_WAIT1()  asm volatile("cp.async.wait_group 1;" ::: "memory")

// ---------------- K1: tensor-core fused LN + left/right projection --------
#define WS_PAD 260
#define AS_PAD 36
#define TR_PAD 132
#define K1_SMEM ((64 * WS_PAD + 128 * AS_PAD) * 4)

__global__ __launch_bounds__(128) void k_ln_proj_tc(
    const float* __restrict__ act, const float* __restrict__ mask,
    const float* __restrict__ ln_s, const float* __restrict__ ln_o,
    const float* __restrict__ lw, const float* __restrict__ lb,
    const float* __restrict__ rw, const float* __restrict__ rb)
{
    extern __shared__ __align__(128) float sm[];
    float* Ws = sm;                        // [64][WS_PAD]
    float* As = sm + 64 * WS_PAD;          // [128][AS_PAD]
    float* tr = sm;                        // [64][TR_PAD]  epilogue overlay

    __shared__ float s_mu[128], s_rs[128], s_m[128];
    __shared__ float s_lns[CM], s_lno[CM], s_bias[64];

    int b  = blockIdx.x;
    int a0 = blockIdx.y * 128;
    int tid = threadIdx.x, warp = tid >> 5, lane = tid & 31;
    int g = lane >> 2, tg = lane & 3;

    for (int i = tid; i < 64 * CM; i += 128) {
        int col = i >> 8, k = i & 255;
        float w = (col < 32) ? lw[k * CO + col] : rw[k * CO + (col - 32)];
        Ws[col * WS_PAD + k] = rna_tf32(w);
    }
    for (int k = tid; k < CM; k += 128) { s_lns[k] = ln_s[k]; s_lno[k] = ln_o[k]; }
    if (tid < 64) s_bias[tid] = (tid < 32) ? lb[tid] : rb[tid - 32];
    s_m[tid] = mask[(size_t)(a0 + tid) * N_RES + b];

    for (int r = warp; r < 128; r += 4) {
        const float* x = act + ((size_t)(a0 + r) * N_RES + b) * CM;
        float s = 0.f, ss = 0.f;
        #pragma unroll
        for (int i = 0; i < 8; i++) {
            float v = x[lane + 32 * i];
            s += v; ss += v * v;
        }
        #pragma unroll
        for (int o = 16; o; o >>= 1) {
            s  += __shfl_xor_sync(0xFFFFFFFFu, s, o);
            ss += __shfl_xor_sync(0xFFFFFFFFu, ss, o);
        }
        if (lane == 0) {
            float mu = s * (1.0f / CM);
            float var = ss * (1.0f / CM) - mu * mu;
            s_mu[r] = mu;
            s_rs[r] = rsqrtf(var + LN_EPS);
        }
    }
    __syncthreads();

    float acc[2][8][4] = {};
    int lr = tid >> 3, lq = tid & 7;

    for (int kc = 0; kc < 8; kc++) {
        int k0 = kc * 32;
        #pragma unroll
        for (int j = 0; j < 8; j++) {
            int r = lr + 16 * j;
            float4 v = *(const float4*)(act + ((size_t)(a0 + r) * N_RES + b) * CM + k0 + lq * 4);
            float mu = s_mu[r], rs = s_rs[r];
            int k = k0 + lq * 4;
            float4 o;
            o.x = rna_tf32((v.x - mu) * rs * s_lns[k + 0] + s_lno[k + 0]);
            o.y = rna_tf32((v.y - mu) * rs * s_lns[k + 1] + s_lno[k + 1]);
            o.z = rna_tf32((v.z - mu) * rs * s_lns[k + 2] + s_lno[k + 2]);
            o.w = rna_tf32((v.w - mu) * rs * s_lns[k + 3] + s_lno[k + 3]);
            *(float4*)&As[r * AS_PAD + lq * 4] = o;
        }
        __syncthreads();
        #pragma unroll
        for (int k8 = 0; k8 < 4; k8++) {
            int kk = k8 * 8 + tg;
            uint32_t af[2][4], bf[8][2];
            #pragma unroll
            for (int mi = 0; mi < 2; mi++) {
                int r = (warp * 32 + mi * 16 + g) * AS_PAD;
                af[mi][0] = __float_as_uint(As[r + kk]);
                af[mi][1] = __float_as_uint(As[r + 8 * AS_PAD + kk]);
                af[mi][2] = __float_as_uint(As[r + kk + 4]);
                af[mi][3] = __float_as_uint(As[r + 8 * AS_PAD + kk + 4]);
            }
            #pragma unroll
            for (int ni = 0; ni < 8; ni++) {
                int rw_ = (ni * 8 + g) * WS_PAD + k0;
                bf[ni][0] = __float_as_uint(Ws[rw_ + kk]);
                bf[ni][1] = __float_as_uint(Ws[rw_ + kk + 4]);
            }
            #pragma unroll
            for (int mi = 0; mi < 2; mi++)
                #pragma unroll
                for (int ni = 0; ni < 8; ni++)
                    mma8(acc[mi][ni], af[mi], bf[ni]);
        }
        __syncthreads();
    }

    #pragma unroll
    for (int mi = 0; mi < 2; mi++) {
        int r0 = warp * 32 + mi * 16 + g;
        float m0v = s_m[r0], m1v = s_m[r0 + 8];
        #pragma unroll
        for (int ni = 0; ni < 8; ni++) {
            int c = ni * 8 + 2 * tg;
            float b0 = s_bias[c], b1 = s_bias[c + 1];
            tr[c * TR_PAD + r0]           = rna_tf32(m0v * (acc[mi][ni][0] + b0));
            tr[(c + 1) * TR_PAD + r0]     = rna_tf32(m0v * (acc[mi][ni][1] + b1));
            tr[c * TR_PAD + r0 + 8]       = rna_tf32(m1v * (acc[mi][ni][2] + b0));
            tr[(c + 1) * TR_PAD + r0 + 8] = rna_tf32(m1v * (acc[mi][ni][3] + b1));
        }
    }
    __syncthreads();
    #pragma unroll 4
    for (int cc = 0; cc < 32; cc++)
        g_L[(size_t)(b * CO + cc) * N_SEQ + a0 + tid] = tr[cc * TR_PAD + tid];
    #pragma unroll 4
    for (int cc = 0; cc < 32; cc++)
        g_R[(size_t)(b * CO + cc) * N_SEQ + a0 + tid] = tr[(32 + cc) * TR_PAD + tid];
}

// ---------------- K0: norm[b][d] = sum_a mask[a,b]*mask[a,d] --------------
__global__ __launch_bounds__(512) void k_norm(const float* __restrict__ mask)
{
    int b = blockIdx.x;
    __shared__ float mcol[N_SEQ];
    for (int a = threadIdx.x; a < N_SEQ; a += blockDim.x)
        mcol[a] = mask[a * N_RES + b];
    __syncthreads();
    for (int d = threadIdx.x; d < N_RES; d += blockDim.x) {
        float acc = 0.f;
        #pragma unroll 8
        for (int a = 0; a < N_SEQ; a++)
            acc = fmaf(mcol[a], mask[a * N_RES + d], acc);
        g_norm[b * N_RES + d] = acc;
    }
}

// ---------------- W transpose: WtT[f][c*32+e] = rna(W[c][e][f]) -----------
__global__ __launch_bounds__(256) void k_twT(const float* __restrict__ W)
{
    int f = blockIdx.x;                    // 0..127
    for (int k = threadIdx.x; k < 1024; k += 256)
        g_WtT[f * 1024 + k] = rna_tf32(W[k * CZ + f]);   // k = c*32+e
}

// ---------------- Stage A+B fused: tile 128bc x 256de, then out proj ------
// Mainloop: 8 warps (2x4), warp tile 64x64, 3-stage cp.async ring, one sync,
// ldmatrix frags + pipelined k8.  Epilogue: P[32 bd][1024 ce] in smem, GEMM
// vs WtT chunks (64k double-buffered), bias + /(EPS+norm), direct out store.
#define A_ROWSZ 36
#define SA_A (128 * A_ROWSZ)
#define SA_B (256 * A_ROWSZ)
#define SA_STG (SA_A + SA_B)
#define P_STRIDE 1028
#define BS2_OFF  (32 * P_STRIDE)          /* 32896 floats */
#define BS2_STRIDE (128 * 68)             /* 8704 floats per W chunk buf */
#define SA_TOTAL ((BS2_OFF + 2 * BS2_STRIDE) * 4)   /* 201216 B */

__global__ __launch_bounds__(256, 1) void k_outer_mma(
    const float* __restrict__ ob, float* __restrict__ out)
{
    extern __shared__ __align__(128) float sm[];

    int tid = threadIdx.x;
    int m0 = blockIdx.y * 128;
    int n0 = blockIdx.x * 256;
    int warp = tid >> 5, lane = tid & 31;
    int wm = warp >> 2, wn = warp & 3;      // 2 x 4
    int g = lane >> 2, tg = lane & 3;

    float acc[4][8][4] = {};

    int r8 = tid >> 3, q = tid & 7;         // loader coords

    uint32_t sb = (uint32_t)__cvta_generic_to_shared(sm);
    int rowA = wm * 64 + (lane & 15);
    int colA = ((lane >> 4) & 1) * 4;
    uint32_t aoff = (uint32_t)((rowA * A_ROWSZ + colA) * 4);
    int rowB = wn * 64 + (lane & 7) + ((lane >> 4) & 1) * 8;
    int colB = ((lane >> 3) & 1) * 4;
    uint32_t boff = (uint32_t)((rowB * A_ROWSZ + colB) * 4) + SA_A * 4u;
    uint32_t ldst = sb + (uint32_t)((r8 * A_ROWSZ + q * 4) * 4);

    // prologue: stages 0,1 <- ktiles 0,1
    #pragma unroll
    for (int kt = 0; kt < 2; kt++) {
        uint32_t soff = (uint32_t)kt * (SA_STG * 4);
        const float* asrc = g_L + (size_t)(m0 + r8) * N_SEQ + kt * 32 + q * 4;
        #pragma unroll
        for (int j = 0; j < 4; j++)
            cpa16(ldst + soff + j * (32 * A_ROWSZ * 4), asrc + (size_t)(32 * j) * N_SEQ);
        const float* bsrc = g_R + (size_t)(n0 + r8) * N_SEQ + kt * 32 + q * 4;
        #pragma unroll
        for (int j = 0; j < 8; j++)
            cpa16(ldst + soff + SA_A * 4u + j * (32 * A_ROWSZ * 4), bsrc + (size_t)(32 * j) * N_SEQ);
        CP_COMMIT();
    }

    int stg = 0;
    uint32_t stgoff = 0;
    for (int kt = 0; kt < 16; kt++) {
        CP_WAIT1();
        __syncthreads();

        if (kt + 2 < 16) {
            int ns = stg + 2; if (ns >= 3) ns -= 3;
            uint32_t noff = (uint32_t)ns * (SA_STG * 4);
            const float* asrc = g_L + (size_t)(m0 + r8) * N_SEQ + (kt + 2) * 32 + q * 4;
            #pragma unroll
            for (int j = 0; j < 4; j++)
                cpa16(ldst + noff + j * (32 * A_ROWSZ * 4), asrc + (size_t)(32 * j) * N_SEQ);
            const float* bsrc = g_R + (size_t)(n0 + r8) * N_SEQ + (kt + 2) * 32 + q * 4;
            #pragma unroll
            for (int j = 0; j < 8; j++)
                cpa16(ldst + noff + SA_A * 4u + j * (32 * A_ROWSZ * 4), bsrc + (size_t)(32 * j) * N_SEQ);
        }
        CP_COMMIT();

        uint32_t ab = sb + stgoff + aoff;
        uint32_t bb = sb + stgoff + boff;

        uint32_t afr[2][4][4], bfr[2][4][4];
        #pragma unroll
        for (int mi = 0; mi < 4; mi++) ldsm4(afr[0][mi], ab + mi * (16 * A_ROWSZ * 4));
        #pragma unroll
        for (int n2 = 0; n2 < 4; n2++) ldsm4(bfr[0][n2], bb + n2 * (16 * A_ROWSZ * 4));

        #pragma unroll
        for (int k8 = 0; k8 < 4; k8++) {
            int cur = k8 & 1, nxt = cur ^ 1;
            if (k8 < 3) {
                #pragma unroll
                for (int mi = 0; mi < 4; mi++)
                    ldsm4(afr[nxt][mi], ab + mi * (16 * A_ROWSZ * 4) + (k8 + 1) * 32);
                #pragma unroll
                for (int n2 = 0; n2 < 4; n2++)
                    ldsm4(bfr[nxt][n2], bb + n2 * (16 * A_ROWSZ * 4) + (k8 + 1) * 32);
            }
            #pragma unroll
            for (int mi = 0; mi < 4; mi++)
                #pragma unroll
                for (int ni = 0; ni < 8; ni++)
                    mma8(acc[mi][ni], afr[cur][mi], &bfr[cur][ni >> 1][(ni & 1) * 2]);
        }

        stg++; if (stg == 3) stg = 0;
        stgoff = (uint32_t)stg * (SA_STG * 4);
    }

    // ===== fused output projection =====
    __syncthreads();                         // all mainloop smem reads done

    // prefetch W chunks 0,1 into Bs2 (beyond P region)
    {
        int fr = tid >> 1, hk = (tid & 1) * 32;
        #pragma unroll
        for (int ch = 0; ch < 2; ch++) {
            uint32_t dst = sb + (uint32_t)((BS2_OFF + ch * BS2_STRIDE + fr * 68 + hk) * 4);
            const float* src = g_WtT + (size_t)fr * 1024 + ch * 64 + hk;
            #pragma unroll
            for (int j = 0; j < 8; j++)
                cpa16(dst + j * 16, src + j * 4);
            CP_COMMIT();
        }
    }

    // write P[r=(b'*8+d')][k=(c*32+e)] = rna(acc)
    #pragma unroll
    for (int mi = 0; mi < 4; mi++) {
        int m = wm * 64 + mi * 16 + g;
        #pragma unroll
        for (int ni = 0; ni < 8; ni++) {
            int n = wn * 64 + ni * 8 + 2 * tg;
            int r0 = (m >> 5) * 8 + (n >> 5);
            int k0 = (m & 31) * 32 + (n & 31);
            float2 v;
            v.x = rna_tf32(acc[mi][ni][0]); v.y = rna_tf32(acc[mi][ni][1]);
            *(float2*)&sm[r0 * P_STRIDE + k0] = v;
            int m1 = m + 8;
            int r1 = (m1 >> 5) * 8 + (n >> 5);
            int k1 = (m1 & 31) * 32 + (n & 31);
            v.x = rna_tf32(acc[mi][ni][2]); v.y = rna_tf32(acc[mi][ni][3]);
            *(float2*)&sm[r1 * P_STRIDE + k1] = v;
        }
    }

    // epilogue GEMM: [32 x 1024] @ [1024 x 128]
    float acc2[4][4] = {};
    uint32_t paoff = sb + (uint32_t)(((wm * 16 + (lane & 15)) * P_STRIDE
                                     + ((lane >> 4) & 1) * 4) * 4);
    int fRow = wn * 32 + (lane & 7) + ((lane >> 4) & 1) * 8;
    uint32_t pboff = sb + (uint32_t)((BS2_OFF + fRow * 68 + ((lane >> 3) & 1) * 4) * 4);
    int lfr = tid >> 1, lhk = (tid & 1) * 32;

    for (int ch = 0; ch < 16; ch++) {
        CP_WAIT1();
        __syncthreads();

        uint32_t ab = paoff + (uint32_t)(ch * 256);
        uint32_t bb = pboff + (uint32_t)((ch & 1) * (BS2_STRIDE * 4));

        uint32_t af2[2][4], bf2[2][2][4];
        ldsm4(af2[0], ab);
        ldsm4(bf2[0][0], bb);
        ldsm4(bf2[0][1], bb + 16 * 68 * 4);

        #pragma unroll
        for (int k8 = 0; k8 < 8; k8++) {
            int cur = k8 & 1, nxt = cur ^ 1;
            if (k8 < 7) {
                ldsm4(af2[nxt], ab + (k8 + 1) * 32);
                ldsm4(bf2[nxt][0], bb + (k8 + 1) * 32);
                ldsm4(bf2[nxt][1], bb + 16 * 68 * 4 + (k8 + 1) * 32);
            }
            #pragma unroll
            for (int n16 = 0; n16 < 2; n16++)
                #pragma unroll
                for (int sub = 0; sub < 2; sub++)
                    mma8(acc2[n16 * 2 + sub], af2[cur], &bf2[cur][n16][sub * 2]);
        }

        __syncthreads();
        if (ch + 2 < 16) {
            uint32_t dst = sb + (uint32_t)((BS2_OFF + (ch & 1) * BS2_STRIDE
                                            + lfr * 68 + lhk) * 4);
            const float* src = g_WtT + (size_t)lfr * 1024 + (ch + 2) * 64 + lhk;
            #pragma unroll
            for (int j = 0; j < 8; j++)
                cpa16(dst + j * 16, src + j * 4);
        }
        CP_COMMIT();
    }

    // bias + /(EPS+norm) + out store
    int b0 = blockIdx.y * 4, d0 = blockIdx.x * 8;
    #pragma unroll
    for (int half = 0; half < 2; half++) {
        int r = wm * 16 + g + half * 8;
        int bg = b0 + (r >> 3), dg = d0 + (r & 7);
        float inv = 1.0f / (EPS + g_norm[bg * N_RES + dg]);
        size_t o = ((size_t)bg * N_RES + dg) * CZ;
        #pragma unroll
        for (int ni = 0; ni < 4; ni++) {
            int f = wn * 32 + ni * 8 + 2 * tg;
            float2 v;
            v.x = (acc2[ni][half * 2 + 0] + ob[f]) * inv;
            v.y = (acc2[ni][half * 2 + 1] + ob[f + 1]) * inv;
            *(float2*)&out[o + f] = v;
        }
    }
}

// ---------------- launch ----------------
extern "C" void kernel_launch(void* const* d_in, const int* in_sizes, int n_in,
                              void* d_out, int out_size)
{
    const float* act  = (const float*)d_in[0];
    const float* mask = (const float*)d_in[1];
    const float* ln_s = (const float*)d_in[2];
    const float* ln_o = (const float*)d_in[3];
    const float* lw   = (const float*)d_in[4];
    const float* lb   = (const float*)d_in[5];
    const float* rw   = (const float*)d_in[6];
    const float* rb   = (const float*)d_in[7];
    const float* ow   = (const float*)d_in[8];
    const float* ob   = (const float*)d_in[9];
    float* out = (float*)d_out;

    static int once = 0;
    if (!once) {
        cudaFuncSetAttribute(k_ln_proj_tc, cudaFuncAttributeMaxDynamicSharedMemorySize, K1_SMEM);
        cudaFuncSetAttribute(k_outer_mma, cudaFuncAttributeMaxDynamicSharedMemorySize, SA_TOTAL);
        once = 1;
    }

    k_ln_proj_tc<<<dim3(N_RES, N_SEQ / 128), 128, K1_SMEM>>>(
        act, mask, ln_s, ln_o, lw, lb, rw, rb);
    k_norm<<<N_RES, 512>>>(mask);
    k_twT<<<CZ, 256>>>(ow);
    k_outer_mma<<<dim3(BC / 256, BC / 128), 256, SA_TOTAL>>>(ob, out);
}

// round 16
// speedup vs baseline: 1.3277x; 1.3277x over previous
#include <cuda_runtime.h>
#include <cstdint>

#define N_SEQ 512
#define N_RES 384
#define CM    256
#define CO    32
#define CZ    128
#define BC    12288          /* N_RES * CO */
#define LN_EPS 1e-5f
#define EPS    1e-3f

// ---------------- scratch (__device__ globals: alloc-free) ----------------
__device__ float g_L[(size_t)BC * N_SEQ];      // [bc][a]  K-major  (25 MB)
__device__ float g_R[(size_t)BC * N_SEQ];      // [de][a]  K-major  (25 MB)
__device__ float g_inter[(size_t)BC * BC];     // [bc][de]          (604 MB)
__device__ float g_norm[N_RES * N_RES];        // [b][d]
__device__ float g_Wt[CO * CZ * CO];           // [c][f][e]

// ---------------- helpers ----------------
__device__ __forceinline__ float rna_tf32(float x) {
    float y;
    asm("cvt.rna.tf32.f32 %0, %1;" : "=f"(y) : "f"(x));
    return y;
}
__device__ __forceinline__ void mma8(float d[4], const uint32_t a[4], const uint32_t b[2]) {
    asm volatile(
        "mma.sync.aligned.m16n8k8.row.col.f32.tf32.tf32.f32 "
        "{%0,%1,%2,%3}, {%4,%5,%6,%7}, {%8,%9}, {%0,%1,%2,%3};\n"
        : "+f"(d[0]), "+f"(d[1]), "+f"(d[2]), "+f"(d[3])
        : "r"(a[0]), "r"(a[1]), "r"(a[2]), "r"(a[3]),
          "r"(b[0]), "r"(b[1]));
}
__device__ __forceinline__ void ldsm4(uint32_t r[4], uint32_t addr) {
    asm volatile("ldmatrix.sync.aligned.m8n8.x4.shared.b16 {%0,%1,%2,%3}, [%4];"
        : "=r"(r[0]), "=r"(r[1]), "=r"(r[2]), "=r"(r[3]) : "r"(addr));
}
__device__ __forceinline__ void cpa16(uint32_t dst, const void* src) {
    asm volatile("cp.async.cg.shared.global [%0], [%1], 16;" :: "r"(dst), "l"(src));
}
#define CP_COMMIT() asm volatile("cp.async.commit_group;" ::: "memory")
#define CP_WAIT1()  asm volatile("cp.async.wait_group 1;" ::: "memory")

// ---------------- K1: tensor-core fused LN + left/right projection --------
#define WS_PAD 260
#define AS_PAD 36
#define TR_PAD 132
#define K1_SMEM ((64 * WS_PAD + 128 * AS_PAD) * 4)

__global__ __launch_bounds__(128) void k_ln_proj_tc(
    const float* __restrict__ act, const float* __restrict__ mask,
    const float* __restrict__ ln_s, const float* __restrict__ ln_o,
    const float* __restrict__ lw, const float* __restrict__ lb,
    const float* __restrict__ rw, const float* __restrict__ rb)
{
    extern __shared__ __align__(128) float sm[];
    float* Ws = sm;                        // [64][WS_PAD]
    float* As = sm + 64 * WS_PAD;          // [128][AS_PAD]
    float* tr = sm;                        // [64][TR_PAD]  epilogue overlay

    __shared__ float s_mu[128], s_rs[128], s_m[128];
    __shared__ float s_lns[CM], s_lno[CM], s_bias[64];

    int b  = blockIdx.x;
    int a0 = blockIdx.y * 128;
    int tid = threadIdx.x, warp = tid >> 5, lane = tid & 31;
    int g = lane >> 2, tg = lane & 3;

    for (int i = tid; i < 64 * CM; i += 128) {
        int col = i >> 8, k = i & 255;
        float w = (col < 32) ? lw[k * CO + col] : rw[k * CO + (col - 32)];
        Ws[col * WS_PAD + k] = rna_tf32(w);
    }
    for (int k = tid; k < CM; k += 128) { s_lns[k] = ln_s[k]; s_lno[k] = ln_o[k]; }
    if (tid < 64) s_bias[tid] = (tid < 32) ? lb[tid] : rb[tid - 32];
    s_m[tid] = mask[(size_t)(a0 + tid) * N_RES + b];

    for (int r = warp; r < 128; r += 4) {
        const float* x = act + ((size_t)(a0 + r) * N_RES + b) * CM;
        float s = 0.f, ss = 0.f;
        #pragma unroll
        for (int i = 0; i < 8; i++) {
            float v = x[lane + 32 * i];
            s += v; ss += v * v;
        }
        #pragma unroll
        for (int o = 16; o; o >>= 1) {
            s  += __shfl_xor_sync(0xFFFFFFFFu, s, o);
            ss += __shfl_xor_sync(0xFFFFFFFFu, ss, o);
        }
        if (lane == 0) {
            float mu = s * (1.0f / CM);
            float var = ss * (1.0f / CM) - mu * mu;
            s_mu[r] = mu;
            s_rs[r] = rsqrtf(var + LN_EPS);
        }
    }
    __syncthreads();

    float acc[2][8][4] = {};
    int lr = tid >> 3, lq = tid & 7;

    for (int kc = 0; kc < 8; kc++) {
        int k0 = kc * 32;
        #pragma unroll
        for (int j = 0; j < 8; j++) {
            int r = lr + 16 * j;
            float4 v = *(const float4*)(act + ((size_t)(a0 + r) * N_RES + b) * CM + k0 + lq * 4);
            float mu = s_mu[r], rs = s_rs[r];
            int k = k0 + lq * 4;
            float4 o;
            o.x = rna_tf32((v.x - mu) * rs * s_lns[k + 0] + s_lno[k + 0]);
            o.y = rna_tf32((v.y - mu) * rs * s_lns[k + 1] + s_lno[k + 1]);
            o.z = rna_tf32((v.z - mu) * rs * s_lns[k + 2] + s_lno[k + 2]);
            o.w = rna_tf32((v.w - mu) * rs * s_lns[k + 3] + s_lno[k + 3]);
            *(float4*)&As[r * AS_PAD + lq * 4] = o;
        }
        __syncthreads();
        #pragma unroll
        for (int k8 = 0; k8 < 4; k8++) {
            int kk = k8 * 8 + tg;
            uint32_t af[2][4], bf[8][2];
            #pragma unroll
            for (int mi = 0; mi < 2; mi++) {
                int r = (warp * 32 + mi * 16 + g) * AS_PAD;
                af[mi][0] = __float_as_uint(As[r + kk]);
                af[mi][1] = __float_as_uint(As[r + 8 * AS_PAD + kk]);
                af[mi][2] = __float_as_uint(As[r + kk + 4]);
                af[mi][3] = __float_as_uint(As[r + 8 * AS_PAD + kk + 4]);
            }
            #pragma unroll
            for (int ni = 0; ni < 8; ni++) {
                int rw_ = (ni * 8 + g) * WS_PAD + k0;
                bf[ni][0] = __float_as_uint(Ws[rw_ + kk]);
                bf[ni][1] = __float_as_uint(Ws[rw_ + kk + 4]);
            }
            #pragma unroll
            for (int mi = 0; mi < 2; mi++)
                #pragma unroll
                for (int ni = 0; ni < 8; ni++)
                    mma8(acc[mi][ni], af[mi], bf[ni]);
        }
        __syncthreads();
    }

    #pragma unroll
    for (int mi = 0; mi < 2; mi++) {
        int r0 = warp * 32 + mi * 16 + g;
        float m0v = s_m[r0], m1v = s_m[r0 + 8];
        #pragma unroll
        for (int ni = 0; ni < 8; ni++) {
            int c = ni * 8 + 2 * tg;
            float b0 = s_bias[c], b1 = s_bias[c + 1];
            tr[c * TR_PAD + r0]           = rna_tf32(m0v * (acc[mi][ni][0] + b0));
            tr[(c + 1) * TR_PAD + r0]     = rna_tf32(m0v * (acc[mi][ni][1] + b1));
            tr[c * TR_PAD + r0 + 8]       = rna_tf32(m1v * (acc[mi][ni][2] + b0));
            tr[(c + 1) * TR_PAD + r0 + 8] = rna_tf32(m1v * (acc[mi][ni][3] + b1));
        }
    }
    __syncthreads();
    #pragma unroll 4
    for (int cc = 0; cc < 32; cc++)
        g_L[(size_t)(b * CO + cc) * N_SEQ + a0 + tid] = tr[cc * TR_PAD + tid];
    #pragma unroll 4
    for (int cc = 0; cc < 32; cc++)
        g_R[(size_t)(b * CO + cc) * N_SEQ + a0 + tid] = tr[(32 + cc) * TR_PAD + tid];
}

// ---------------- K0: norm[b][d] = sum_a mask[a,b]*mask[a,d] --------------
__global__ __launch_bounds__(512) void k_norm(const float* __restrict__ mask)
{
    int b = blockIdx.x;
    __shared__ float mcol[N_SEQ];
    for (int a = threadIdx.x; a < N_SEQ; a += blockDim.x)
        mcol[a] = mask[a * N_RES + b];
    __syncthreads();
    for (int d = threadIdx.x; d < N_RES; d += blockDim.x) {
        float acc = 0.f;
        #pragma unroll 8
        for (int a = 0; a < N_SEQ; a++)
            acc = fmaf(mcol[a], mask[a * N_RES + d], acc);
        g_norm[b * N_RES + d] = acc;
    }
}

// ---------------- W transpose: Wt[c][f][e] = W[c][e][f] -------------------
__global__ __launch_bounds__(256) void k_tw(const float* __restrict__ W)
{
    int c = blockIdx.x;
    for (int i = threadIdx.x; i < CZ * CO; i += 256) {
        int f = i >> 5, e = i & 31;
        g_Wt[c * CZ * CO + i] = rna_tf32(W[c * CO * CZ + e * CZ + f]);
    }
}

// ---------------- Stage A: inter = L^T R, tile 128m x 256n, BK=64 ---------
// 8 warps (2x4), warp tile 64x64, 2-stage cp.async double buffer (2 syncs),
// ldmatrix frags + 8-step pipelined k8. 204 KB smem, 1 CTA/SM.
#define A2_ROW 68                          /* 64 + 4 pad floats per row */
#define SA_A (128 * A2_ROW)
#define SA_B (256 * A2_ROW)
#define SA_STG (SA_A + SA_B)               /* 26112 floats */
#define SA_TOTAL (2 * SA_STG * 4)          /* 208896 B */

__global__ __launch_bounds__(256, 1) void k_outer_mma()
{
    extern __shared__ __align__(128) float sm[];

    int tid = threadIdx.x;
    int m0 = blockIdx.y * 128;
    int n0 = blockIdx.x * 256;
    int warp = tid >> 5, lane = tid & 31;
    int wm = warp >> 2, wn = warp & 3;      // 2 x 4
    int g = lane >> 2, tg = lane & 3;

    float acc[4][8][4] = {};

    int r4 = tid >> 4, q = tid & 15;        // loader: 16 rows x 16 float4-cols

    uint32_t sb = (uint32_t)__cvta_generic_to_shared(sm);
    int rowA = wm * 64 + (lane & 15);
    int colA = ((lane >> 4) & 1) * 4;
    uint32_t aoff = (uint32_t)((rowA * A2_ROW + colA) * 4);
    int rowB = wn * 64 + (lane & 7) + ((lane >> 4) & 1) * 8;
    int colB = ((lane >> 3) & 1) * 4;
    uint32_t boff = (uint32_t)((rowB * A2_ROW + colB) * 4) + SA_A * 4u;
    uint32_t ldst = sb + (uint32_t)((r4 * A2_ROW + q * 4) * 4);

    // prologue: ktiles 0,1 -> stages 0,1
    #pragma unroll
    for (int kt = 0; kt < 2; kt++) {
        uint32_t soff = (uint32_t)kt * (SA_STG * 4);
        const float* asrc = g_L + (size_t)(m0 + r4) * N_SEQ + kt * 64 + q * 4;
        #pragma unroll
        for (int j = 0; j < 8; j++)
            cpa16(ldst + soff + j * (16 * A2_ROW * 4), asrc + (size_t)(16 * j) * N_SEQ);
        const float* bsrc = g_R + (size_t)(n0 + r4) * N_SEQ + kt * 64 + q * 4;
        #pragma unroll
        for (int j = 0; j < 16; j++)
            cpa16(ldst + soff + SA_A * 4u + j * (16 * A2_ROW * 4), bsrc + (size_t)(16 * j) * N_SEQ);
        CP_COMMIT();
    }

    for (int kt = 0; kt < 8; kt++) {
        CP_WAIT1();
        __syncthreads();
        int buf = kt & 1;
        uint32_t stgoff = (uint32_t)buf * (SA_STG * 4);
        uint32_t ab = sb + stgoff + aoff;
        uint32_t bb = sb + stgoff + boff;

        uint32_t afr[2][4][4], bfr[2][4][4];
        #pragma unroll
        for (int mi = 0; mi < 4; mi++) ldsm4(afr[0][mi], ab + mi * (16 * A2_ROW * 4));
        #pragma unroll
        for (int n2 = 0; n2 < 4; n2++) ldsm4(bfr[0][n2], bb + n2 * (16 * A2_ROW * 4));

        #pragma unroll
        for (int k8 = 0; k8 < 8; k8++) {
            int cur = k8 & 1, nxt = cur ^ 1;
            if (k8 < 7) {
                #pragma unroll
                for (int mi = 0; mi < 4; mi++)
                    ldsm4(afr[nxt][mi], ab + mi * (16 * A2_ROW * 4) + (k8 + 1) * 32);
                #pragma unroll
                for (int n2 = 0; n2 < 4; n2++)
                    ldsm4(bfr[nxt][n2], bb + n2 * (16 * A2_ROW * 4) + (k8 + 1) * 32);
            }
            #pragma unroll
            for (int mi = 0; mi < 4; mi++)
                #pragma unroll
                for (int ni = 0; ni < 8; ni++)
                    mma8(acc[mi][ni], afr[cur][mi], &bfr[cur][ni >> 1][(ni & 1) * 2]);
        }
        __syncthreads();
        if (kt + 2 < 8) {
            uint32_t soff = (uint32_t)buf * (SA_STG * 4);
            const float* asrc = g_L + (size_t)(m0 + r4) * N_SEQ + (kt + 2) * 64 + q * 4;
            #pragma unroll
            for (int j = 0; j < 8; j++)
                cpa16(ldst + soff + j * (16 * A2_ROW * 4), asrc + (size_t)(16 * j) * N_SEQ);
            const float* bsrc = g_R + (size_t)(n0 + r4) * N_SEQ + (kt + 2) * 64 + q * 4;
            #pragma unroll
            for (int j = 0; j < 16; j++)
                cpa16(ldst + soff + SA_A * 4u + j * (16 * A2_ROW * 4), bsrc + (size_t)(16 * j) * N_SEQ);
        }
        CP_COMMIT();
    }

    // epilogue: tf32-round and store (streaming, evict-first)
    #pragma unroll
    for (int mi = 0; mi < 4; mi++) {
        size_t r0 = (size_t)(m0 + wm * 64 + mi * 16 + g) * BC;
        #pragma unroll
        for (int ni = 0; ni < 8; ni++) {
            int cN = n0 + wn * 64 + ni * 8 + 2 * tg;
            float2 v;
            v.x = rna_tf32(acc[mi][ni][0]); v.y = rna_tf32(acc[mi][ni][1]);
            __stcs((float2*)&g_inter[r0 + cN], v);
            v.x = rna_tf32(acc[mi][ni][2]); v.y = rna_tf32(acc[mi][ni][3]);
            __stcs((float2*)&g_inter[r0 + (size_t)8 * BC + cN], v);
        }
    }
}

// ---------------- Stage B: out[b][d][f], tile 128d x 128f, K=1024 ---------
// 3-stage ring, one sync per c, 2 CTAs/SM.  (R11 config, unchanged)
#define A_ROWSZ 36
#define SB_A (128 * A_ROWSZ)
#define SB_STG (2 * SB_A)
#define SB_TOTAL (3 * SB_STG * 4)

__global__ __launch_bounds__(128, 2) void k_proj_mma(
    const float* __restrict__ ob, float* __restrict__ out)
{
    extern __shared__ __align__(128) float sm[];

    int tid = threadIdx.x;
    int b  = blockIdx.y;
    int d0 = blockIdx.x * 128;
    int warp = tid >> 5, lane = tid & 31;
    int wm = warp >> 1, wn = warp & 1;      // 2 x 2
    int g = lane >> 2, tg = lane & 3;

    float acc[4][8][4] = {};

    int r8 = tid >> 3, q = tid & 7;

    uint32_t sb = (uint32_t)__cvta_generic_to_shared(sm);
    int rowA = wm * 64 + (lane & 15);
    int colA = ((lane >> 4) & 1) * 4;
    uint32_t aoff = (uint32_t)((rowA * A_ROWSZ + colA) * 4);
    int rowB = wn * 64 + (lane & 7) + ((lane >> 4) & 1) * 8;
    int colB = ((lane >> 3) & 1) * 4;
    uint32_t boff = (uint32_t)((rowB * A_ROWSZ + colB) * 4) + SB_A * 4u;
    uint32_t ldst = sb + (uint32_t)((r8 * A_ROWSZ + q * 4) * 4);

    #pragma unroll
    for (int c = 0; c < 2; c++) {
        uint32_t soff = (uint32_t)c * (SB_STG * 4);
        const float* asrc = g_inter + (size_t)(b * CO + c) * BC + (size_t)(d0 + r8) * 32 + q * 4;
        #pragma unroll
        for (int j = 0; j < 8; j++)
            cpa16(ldst + soff + j * (16 * A_ROWSZ * 4), asrc + (size_t)(16 * j) * 32);
        const float* bsrc = g_Wt + c * CZ * CO + r8 * 32 + q * 4;
        #pragma unroll
        for (int j = 0; j < 8; j++)
            cpa16(ldst + soff + SB_A * 4u + j * (16 * A_ROWSZ * 4), bsrc + (size_t)(16 * j) * 32);
        CP_COMMIT();
    }

    int stg = 0;
    uint32_t stgoff = 0;
    for (int c = 0; c < 32; c++) {
        CP_WAIT1();
        __syncthreads();

        if (c + 2 < 32) {
            int ns = stg + 2; if (ns >= 3) ns -= 3;
            uint32_t noff = (uint32_t)ns * (SB_STG * 4);
            const float* asrc = g_inter + (size_t)(b * CO + c + 2) * BC + (size_t)(d0 + r8) * 32 + q * 4;
            #pragma unroll
            for (int j = 0; j < 8; j++)
                cpa16(ldst + noff + j * (16 * A_ROWSZ * 4), asrc + (size_t)(16 * j) * 32);
            const float* bsrc = g_Wt + (c + 2) * CZ * CO + r8 * 32 + q * 4;
            #pragma unroll
            for (int j = 0; j < 8; j++)
                cpa16(ldst + noff + SB_A * 4u + j * (16 * A_ROWSZ * 4), bsrc + (size_t)(16 * j) * 32);
        }
        CP_COMMIT();

        uint32_t ab = sb + stgoff + aoff;
        uint32_t bb = sb + stgoff + boff;

        uint32_t afr[2][4][4], bfr[2][4][4];
        #pragma unroll
        for (int mi = 0; mi < 4; mi++) ldsm4(afr[0][mi], ab + mi * (16 * A_ROWSZ * 4));
        #pragma unroll
        for (int n2 = 0; n2 < 4; n2++) ldsm4(bfr[0][n2], bb + n2 * (16 * A_ROWSZ * 4));

        #pragma unroll
        for (int k8 = 0; k8 < 4; k8++) {
            int cur = k8 & 1, nxt = cur ^ 1;
            if (k8 < 3) {
                #pragma unroll
                for (int mi = 0; mi < 4; mi++)
                    ldsm4(afr[nxt][mi], ab + mi * (16 * A_ROWSZ * 4) + (k8 + 1) * 32);
                #pragma unroll
                for (int n2 = 0; n2 < 4; n2++)
                    ldsm4(bfr[nxt][n2], bb + n2 * (16 * A_ROWSZ * 4) + (k8 + 1) * 32);
            }
            #pragma unroll
            for (int mi = 0; mi < 4; mi++)
                #pragma unroll
                for (int ni = 0; ni < 8; ni++)
                    mma8(acc[mi][ni], afr[cur][mi], &bfr[cur][ni >> 1][(ni & 1) * 2]);
        }

        stg++; if (stg == 3) stg = 0;
        stgoff = (uint32_t)stg * (SB_STG * 4);
    }

    // epilogue: + bias, / (EPS + norm)
    #pragma unroll
    for (int mi = 0; mi < 4; mi++) {
        int dl = wm * 64 + mi * 16 + g;
        float inv0 = 1.0f / (EPS + g_norm[b * N_RES + d0 + dl]);
        float inv1 = 1.0f / (EPS + g_norm[b * N_RES + d0 + dl + 8]);
        size_t o0 = ((size_t)b * N_RES + d0 + dl) * CZ;
        #pragma unroll
        for (int ni = 0; ni < 8; ni++) {
            int f = wn * 64 + ni * 8 + 2 * tg;
            float b0 = ob[f], b1 = ob[f + 1];
            float2 v;
            v.x = (acc[mi][ni][0] + b0) * inv0;
            v.y = (acc[mi][ni][1] + b1) * inv0;
            *(float2*)&out[o0 + f] = v;
            v.x = (acc[mi][ni][2] + b0) * inv1;
            v.y = (acc[mi][ni][3] + b1) * inv1;
            *(float2*)&out[o0 + (size_t)8 * CZ + f] = v;
        }
    }
}

// ---------------- launch ----------------
extern "C" void kernel_launch(void* const* d_in, const int* in_sizes, int n_in,
                              void* d_out, int out_size)
{
    const float* act  = (const float*)d_in[0];
    const float* mask = (const float*)d_in[1];
    const float* ln_s = (const float*)d_in[2];
    const float* ln_o = (const float*)d_in[3];
    const float* lw   = (const float*)d_in[4];
    const float* lb   = (const float*)d_in[5];
    const float* rw   = (const float*)d_in[6];
    const float* rb   = (const float*)d_in[7];
    const float* ow   = (const float*)d_in[8];
    const float* ob   = (const float*)d_in[9];
    float* out = (float*)d_out;

    static int once = 0;
    if (!once) {
        cudaFuncSetAttribute(k_ln_proj_tc, cudaFuncAttributeMaxDynamicSharedMemorySize, K1_SMEM);
        cudaFuncSetAttribute(k_outer_mma, cudaFuncAttributeMaxDynamicSharedMemorySize, SA_TOTAL);
        cudaFuncSetAttribute(k_proj_mma,  cudaFuncAttributeMaxDynamicSharedMemorySize, SB_TOTAL);
        once = 1;
    }

    k_ln_proj_tc<<<dim3(N_RES, N_SEQ / 128), 128, K1_SMEM>>>(
        act, mask, ln_s, ln_o, lw, lb, rw, rb);
    k_norm<<<N_RES, 512>>>(mask);
    k_tw<<<CO, 256>>>(ow);
    k_outer_mma<<<dim3(BC / 256, BC / 128), 256, SA_TOTAL>>>();
    k_proj_mma<<<dim3(N_RES / 128, N_RES), 128, SB_TOTAL>>>(ob, out);
}